// round 5
// baseline (speedup 1.0000x reference)
#include <cuda_runtime.h>

// ----------------------------------------------------------------------------
// ControlWhile persistent kernel, R4.
//   x = conv1x1(x, w_pre); while mean|x|<3: x = 10*conv(tanh(conv(x,w_sh)),w_lp);
//   out = conv1x1(x, w_sh)
//
// R4 change vs R3 (2228us, DRAM=80%, fma=4%): g_v is now PAIR-MAJOR
// interleaved [pair][16ch] (one contiguous 128B line per pixel-pair) instead of
// channel-planar. Loop-phase traffic becomes pure streaming 128-bit loads and
// stores, L2-resident. Decide step parallelized via smem (fixed summation
// order kept for bit-identical loop decisions in every block).
// ----------------------------------------------------------------------------

#define CIN    3
#define COUT   16
#define HW     147456           // 384*384
#define HWP    73728            // HW/2 (pairs per batch image)
#define NPIX   1179648          // 8*HW
#define NPAIR  589824           // NPIX/2
#define NTOT   18874368.0       // NPIX*COUT elements in v
#define THRESH (3.0 * NTOT)     // mean|v| < 3  <=>  sum|v| < 3*NTOT
#define MAX_IT 64
#define MAX_BLOCKS 1024
#define TPB    512

// v, pair-major: g_v[q*COUT + c] holds f32x2 {pixel 2q, pixel 2q+1} of chan c.
__device__ __align__(16) unsigned long long g_v[(size_t)NPAIR * COUT];
// Per-block |v| partial sums — fully overwritten every phase (replay-safe).
__device__ double g_part[MAX_BLOCKS];
// Grid barrier: count returns to 0; gen monotonic, equality-compared.
__device__ unsigned int g_bar_count;
__device__ volatile unsigned int g_bar_gen;

// ---- packed f32x2 helpers (FFMA2: PTX-only, ptxas won't auto-fuse) ----
__device__ __forceinline__ unsigned long long ffma2(unsigned long long a,
                                                    unsigned long long b,
                                                    unsigned long long c) {
    unsigned long long d;
    asm("fma.rn.f32x2 %0, %1, %2, %3;" : "=l"(d) : "l"(a), "l"(b), "l"(c));
    return d;
}
__device__ __forceinline__ unsigned long long fmul2(unsigned long long a,
                                                    unsigned long long b) {
    unsigned long long d;
    asm("mul.rn.f32x2 %0, %1, %2;" : "=l"(d) : "l"(a), "l"(b));
    return d;
}
__device__ __forceinline__ unsigned long long pack2(float lo, float hi) {
    unsigned long long d;
    asm("mov.b64 %0, {%1, %2};" : "=l"(d) : "f"(lo), "f"(hi));
    return d;
}
__device__ __forceinline__ void unpack2(unsigned long long v, float& lo, float& hi) {
    asm("mov.b64 {%0, %1}, %2;" : "=f"(lo), "=f"(hi) : "l"(v));
}

// tanh via exp (~1e-7 rel err; NOT tanh.approx whose ~6e-4 error could flip
// the data-dependent trip count). Clamp at 9 is exact in fp32.
__device__ __forceinline__ float tanhx(float x) {
    float xc = fminf(fmaxf(x, -9.0f), 9.0f);
    float t  = __expf(xc + xc);
    return __fdividef(t - 1.0f, t + 1.0f);
}

// Software grid barrier (all blocks co-resident: 1 block/SM, verified at launch).
__device__ __forceinline__ void grid_bar() {
    __syncthreads();
    if (threadIdx.x == 0) {
        __threadfence();
        unsigned g = g_bar_gen;
        unsigned a = atomicAdd(&g_bar_count, 1u);
        if (a == gridDim.x - 1) {
            atomicExch(&g_bar_count, 0u);
            __threadfence();
            g_bar_gen = g + 1;
        } else {
            while (g_bar_gen == g) { __nanosleep(64); }
        }
    }
    __syncthreads();
}

// Block-reduce a float partial into g_part[blockIdx.x] (double).
__device__ __forceinline__ void store_block_partial(float part, double* s_wsum) {
    __syncthreads();
    float v = part;
    #pragma unroll
    for (int o = 16; o > 0; o >>= 1) v += __shfl_xor_sync(0xffffffffu, v, o);
    if ((threadIdx.x & 31) == 0) s_wsum[threadIdx.x >> 5] = (double)v;
    __syncthreads();
    if (threadIdx.x == 0) {
        double s = 0.0;
        #pragma unroll
        for (int i = 0; i < TPB / 32; i++) s += s_wsum[i];
        g_part[blockIdx.x] = s;
    }
}

__global__ void __launch_bounds__(TPB, 1)
control_while_kernel(const float* __restrict__ x,
                     const float* __restrict__ wpre, const float* __restrict__ bpre,
                     const float* __restrict__ wloop, const float* __restrict__ bloop,
                     const float* __restrict__ wsh, const float* __restrict__ bsh,
                     float* __restrict__ out)
{
    __shared__ unsigned long long s_wpre[COUT * CIN];
    __shared__ unsigned long long s_wsh[COUT * COUT];
    __shared__ unsigned long long s_wl[COUT * COUT];
    __shared__ unsigned long long s_bpre[COUT], s_bsh[COUT], s_bl[COUT];
    __shared__ double s_wsum[TPB / 32];
    __shared__ double s_pg[MAX_BLOCKS];   // parallel-loaded g_part copies
    __shared__ double s_bcast;

    for (int i = threadIdx.x; i < COUT * COUT; i += TPB) {
        if (i < COUT * CIN) { float w = wpre[i]; s_wpre[i] = pack2(w, w); }
        float w0 = wsh[i];   s_wsh[i] = pack2(w0, w0);
        float w1 = wloop[i]; s_wl[i]  = pack2(w1, w1);
        if (i < COUT) {
            float b0 = bpre[i];  s_bpre[i] = pack2(b0, b0);
            float b1 = bsh[i];   s_bsh[i]  = pack2(b1, b1);
            float b2 = bloop[i]; s_bl[i]   = pack2(b2, b2);
        }
    }
    __syncthreads();

    const int gid    = blockIdx.x * TPB + threadIdx.x;
    const int stride = gridDim.x * TPB;

    // Batch decomposition only needed for x/out (channel-planar). stride can
    // exceed HWP, so rollover is a while-loop (R3 lesson).
    const int b0i = gid / HWP;
    const int r0i = gid - b0i * HWP;

    // ---- phase 0: pre conv 3->16 (x planar -> v pair-major), sum|v| ----
    {
        float part = 0.f;
        int b = b0i, r = r0i;
        for (int q = gid; q < NPAIR; q += stride) {
            const float* xp = x + (size_t)b * (CIN * HW) + (r << 1);
            unsigned long long xin[CIN];
            #pragma unroll
            for (int c = 0; c < CIN; c++)
                xin[c] = *(const unsigned long long*)(xp + (size_t)c * HW);
            ulonglong2* vp2 = (ulonglong2*)(g_v + (size_t)q * COUT);
            #pragma unroll
            for (int o = 0; o < COUT; o += 2) {
                unsigned long long a0 = s_bpre[o], a1 = s_bpre[o + 1];
                #pragma unroll
                for (int c = 0; c < CIN; c++) {
                    a0 = ffma2(s_wpre[o * CIN + c],       xin[c], a0);
                    a1 = ffma2(s_wpre[(o + 1) * CIN + c], xin[c], a1);
                }
                vp2[o >> 1] = make_ulonglong2(a0, a1);
                float l0, h0, l1, h1; unpack2(a0, l0, h0); unpack2(a1, l1, h1);
                part += fabsf(l0) + fabsf(h0) + fabsf(l1) + fabsf(h1);
            }
            r += stride;
            while (r >= HWP) { r -= HWP; b++; }
        }
        store_block_partial(part, s_wsum);
    }
    grid_bar();

    const unsigned long long TEN2 = pack2(10.0f, 10.0f);

    // ---- data-dependent while loop, fully on-device ----
    for (int it = 0; it < MAX_IT; it++) {
        // decide: parallel load of g_part into smem, then fixed-order sum by
        // thread 0 -> identical double in every block -> identical branch.
        if (threadIdx.x < (int)gridDim.x)
            s_pg[threadIdx.x] = ((volatile double*)g_part)[threadIdx.x];
        __syncthreads();
        if (threadIdx.x == 0) {
            double s = 0.0;
            for (int i = 0; i < (int)gridDim.x; i++) s += s_pg[i];
            s_bcast = s;
        }
        __syncthreads();
        double tot = s_bcast;
        __syncthreads();
        if (!(tot < THRESH)) break;   // NaN-safe, same as jnp semantics

        float part = 0.f;
        for (int q = gid; q < NPAIR; q += stride) {
            ulonglong2* vp2 = (ulonglong2*)(g_v + (size_t)q * COUT);
            unsigned long long vin[COUT], h[COUT];
            #pragma unroll
            for (int i = 0; i < COUT / 2; i++) {
                ulonglong2 t = vp2[i];
                vin[2 * i] = t.x; vin[2 * i + 1] = t.y;
            }
            // conv w_shared + tanh
            #pragma unroll
            for (int o = 0; o < COUT; o++) {
                unsigned long long a = s_bsh[o];
                #pragma unroll
                for (int c = 0; c < COUT; c++) a = ffma2(s_wsh[o * COUT + c], vin[c], a);
                float lo, hi; unpack2(a, lo, hi);
                h[o] = pack2(tanhx(lo), tanhx(hi));
            }
            // conv w_loop, *10, store pair-major, accumulate |.|
            #pragma unroll
            for (int o = 0; o < COUT; o += 2) {
                unsigned long long a0 = s_bl[o], a1 = s_bl[o + 1];
                #pragma unroll
                for (int c = 0; c < COUT; c++) {
                    a0 = ffma2(s_wl[o * COUT + c],       h[c], a0);
                    a1 = ffma2(s_wl[(o + 1) * COUT + c], h[c], a1);
                }
                a0 = fmul2(a0, TEN2);
                a1 = fmul2(a1, TEN2);
                vp2[o >> 1] = make_ulonglong2(a0, a1);
                float l0, h0f, l1, h1f; unpack2(a0, l0, h0f); unpack2(a1, l1, h1f);
                part += fabsf(l0) + fabsf(h0f) + fabsf(l1) + fabsf(h1f);
            }
        }
        store_block_partial(part, s_wsum);
        grid_bar();
    }

    // ---- final conv w_shared (v pair-major -> out planar) ----
    {
        int b = b0i, r = r0i;
        for (int q = gid; q < NPAIR; q += stride) {
            const ulonglong2* vp2 = (const ulonglong2*)(g_v + (size_t)q * COUT);
            float* op = out + (size_t)b * (COUT * HW) + (r << 1);
            unsigned long long vin[COUT];
            #pragma unroll
            for (int i = 0; i < COUT / 2; i++) {
                ulonglong2 t = vp2[i];
                vin[2 * i] = t.x; vin[2 * i + 1] = t.y;
            }
            #pragma unroll
            for (int o = 0; o < COUT; o++) {
                unsigned long long a = s_bsh[o];
                #pragma unroll
                for (int c = 0; c < COUT; c++) a = ffma2(s_wsh[o * COUT + c], vin[c], a);
                *(unsigned long long*)(op + (size_t)o * HW) = a;
            }
            r += stride;
            while (r >= HWP) { r -= HWP; b++; }
        }
    }
}

extern "C" void kernel_launch(void* const* d_in, const int* in_sizes, int n_in,
                              void* d_out, int out_size) {
    const float* x     = (const float*)d_in[0];
    const float* wpre  = (const float*)d_in[1];
    const float* bpre  = (const float*)d_in[2];
    const float* wloop = (const float*)d_in[3];
    const float* bloop = (const float*)d_in[4];
    const float* wsh   = (const float*)d_in[5];
    const float* bsh   = (const float*)d_in[6];
    (void)in_sizes; (void)n_in; (void)out_size;

    int dev = 0;
    cudaGetDevice(&dev);
    int sms = 0;
    cudaDeviceGetAttribute(&sms, cudaDevAttrMultiProcessorCount, dev);
    if (sms < 1) sms = 148;

    // Co-residency verified, not assumed: barrier is deadlock-free iff
    // gridDim <= sms * blocksPerSM.
    int occ = 0;
    cudaOccupancyMaxActiveBlocksPerMultiprocessor(&occ, control_while_kernel,
                                                  TPB, 0);
    if (occ < 1) occ = 1;
    long long maxb = (long long)sms * occ;
    int blocks = sms;
    if (blocks > maxb) blocks = (int)maxb;
    if (blocks > MAX_BLOCKS) blocks = MAX_BLOCKS;

    control_while_kernel<<<blocks, TPB>>>(x, wpre, bpre, wloop, bloop, wsh, bsh,
                                          (float*)d_out);
}

// round 6
// speedup vs baseline: 4.5075x; 4.5075x over previous
#include <cuda_runtime.h>

// ----------------------------------------------------------------------------
// ControlWhile persistent kernel, R5.
// R4 post-mortem: DRAM traffic was ~14.5GB/run (~20x algorithmic need) with
// fma=4% -> register SPILLS of the vin[16]+h[16] packed arrays (64 regs of
// arrays at the 128-reg cap) turned every FFMA2 operand into local-memory
// traffic. R5 packs f32x2 along the CHANNEL axis (one pixel per thread):
// arrays shrink to 8+8 packed regs (32 regs), no spills, FFMA2 kept.
// ----------------------------------------------------------------------------

#define CIN    3
#define COUT   16
#define HW     147456           // 384*384
#define NPIX   1179648          // 8*HW
#define NTOT   18874368.0       // NPIX*COUT elements in v
#define THRESH (3.0 * NTOT)     // mean|v| < 3  <=>  sum|v| < 3*NTOT
#define MAX_IT 64
#define MAX_BLOCKS 1024
#define TPB    512

// v, pixel-major packed: g_v[p*8 + j] = f32x2 {chan 2j, chan 2j+1} of pixel p.
__device__ __align__(16) unsigned long long g_v[(size_t)NPIX * 8];
// Per-block |v| partial sums — fully overwritten every phase (replay-safe).
__device__ double g_part[MAX_BLOCKS];
// Grid barrier: count returns to 0; gen monotonic, equality-compared (replay-safe).
__device__ unsigned int g_bar_count;
__device__ volatile unsigned int g_bar_gen;

// ---- packed f32x2 helpers (PTX-only; ptxas won't auto-fuse) ----
__device__ __forceinline__ unsigned long long ffma2(unsigned long long a,
                                                    unsigned long long b,
                                                    unsigned long long c) {
    unsigned long long d;
    asm("fma.rn.f32x2 %0, %1, %2, %3;" : "=l"(d) : "l"(a), "l"(b), "l"(c));
    return d;
}
__device__ __forceinline__ unsigned long long pack2(float lo, float hi) {
    unsigned long long d;
    asm("mov.b64 %0, {%1, %2};" : "=l"(d) : "f"(lo), "f"(hi));
    return d;
}
__device__ __forceinline__ float hadd2(unsigned long long v) {
    float lo, hi;
    asm("mov.b64 {%0, %1}, %2;" : "=f"(lo), "=f"(hi) : "l"(v));
    return lo + hi;
}

// tanh via exp (~1e-7 rel err; NOT tanh.approx whose ~6e-4 error could flip
// the data-dependent trip count). Clamp at 9 is exact in fp32.
__device__ __forceinline__ float tanhx(float x) {
    float xc = fminf(fmaxf(x, -9.0f), 9.0f);
    float t  = __expf(xc + xc);
    return __fdividef(t - 1.0f, t + 1.0f);
}

// Software grid barrier (all blocks co-resident; verified at launch).
__device__ __forceinline__ void grid_bar() {
    __syncthreads();
    if (threadIdx.x == 0) {
        __threadfence();
        unsigned g = g_bar_gen;
        unsigned a = atomicAdd(&g_bar_count, 1u);
        if (a == gridDim.x - 1) {
            atomicExch(&g_bar_count, 0u);
            __threadfence();
            g_bar_gen = g + 1;
        } else {
            while (g_bar_gen == g) { __nanosleep(64); }
        }
    }
    __syncthreads();
}

// Block-reduce a float partial into g_part[blockIdx.x] (double).
__device__ __forceinline__ void store_block_partial(float part, double* s_wsum) {
    __syncthreads();
    float v = part;
    #pragma unroll
    for (int o = 16; o > 0; o >>= 1) v += __shfl_xor_sync(0xffffffffu, v, o);
    if ((threadIdx.x & 31) == 0) s_wsum[threadIdx.x >> 5] = (double)v;
    __syncthreads();
    if (threadIdx.x == 0) {
        double s = 0.0;
        #pragma unroll
        for (int i = 0; i < TPB / 32; i++) s += s_wsum[i];
        g_part[blockIdx.x] = s;
    }
}

__global__ void __launch_bounds__(TPB, 1)
control_while_kernel(const float* __restrict__ x,
                     const float* __restrict__ wpre, const float* __restrict__ bpre,
                     const float* __restrict__ wloop, const float* __restrict__ bloop,
                     const float* __restrict__ wsh, const float* __restrict__ bsh,
                     float* __restrict__ out)
{
    // Channel-pair-packed weights: s_w*2[o*8+j] = (w[o][2j], w[o][2j+1]).
    __shared__ unsigned long long s_wpre2[COUT * 2];
    __shared__ unsigned long long s_wsh2[COUT * 8];
    __shared__ unsigned long long s_wl2[COUT * 8];
    __shared__ float s_bpre[COUT], s_bsh[COUT], s_bl[COUT];
    __shared__ double s_wsum[TPB / 32];
    __shared__ double s_pg[MAX_BLOCKS];
    __shared__ double s_bcast;

    {
        int t = threadIdx.x;
        if (t < COUT * 8) {
            int o = t >> 3, j = t & 7;
            s_wsh2[t] = pack2(wsh[o * COUT + 2 * j],   wsh[o * COUT + 2 * j + 1]);
            s_wl2[t]  = pack2(wloop[o * COUT + 2 * j], wloop[o * COUT + 2 * j + 1]);
        }
        if (t < COUT * 2) {
            int o = t >> 1, j = t & 1;
            s_wpre2[t] = (j == 0) ? pack2(wpre[o * CIN], wpre[o * CIN + 1])
                                  : pack2(wpre[o * CIN + 2], 0.0f);
        }
        if (t < COUT) {
            s_bpre[t] = bpre[t]; s_bsh[t] = bsh[t]; s_bl[t] = bloop[t];
        }
    }
    __syncthreads();

    const int gid    = blockIdx.x * TPB + threadIdx.x;
    const int stride = gridDim.x * TPB;

    // Batch decomposition for planar x/out. stride may exceed any sub-extent:
    // rollover is a while-loop (R3 lesson).
    const int b0i = gid / HW;
    const int i0i = gid - b0i * HW;

    // ---- phase 0: pre conv 3->16 (x planar -> v packed), sum|v| ----
    {
        float part = 0.f;
        int b = b0i, i = i0i;
        for (int q = gid; q < NPIX; q += stride) {
            const float* xp = x + (size_t)b * (CIN * HW) + i;
            float x0 = xp[0], x1 = xp[HW], x2 = xp[2 * HW];
            unsigned long long xin0 = pack2(x0, x1);
            unsigned long long xin1 = pack2(x2, 0.0f);
            ulonglong2* vp2 = (ulonglong2*)(g_v + (size_t)q * 8);
            #pragma unroll
            for (int o = 0; o < COUT; o += 2) {
                unsigned long long a0 = pack2(s_bpre[o], 0.0f);
                unsigned long long a1 = pack2(s_bpre[o + 1], 0.0f);
                a0 = ffma2(s_wpre2[2 * o],     xin0, a0);
                a0 = ffma2(s_wpre2[2 * o + 1], xin1, a0);
                a1 = ffma2(s_wpre2[2 * o + 2], xin0, a1);
                a1 = ffma2(s_wpre2[2 * o + 3], xin1, a1);
                float s0 = hadd2(a0), s1 = hadd2(a1);
                part += fabsf(s0) + fabsf(s1);
                // store pairs two-at-a-time as 128-bit
                if ((o & 2) == 0) vp2[o >> 2].x = pack2(s0, s1);
                else {
                    // complete the ulonglong2 (x written in previous o step)
                    vp2[o >> 2] = make_ulonglong2(vp2[o >> 2].x, pack2(s0, s1));
                }
            }
            i += stride;
            while (i >= HW) { i -= HW; b++; }
        }
        store_block_partial(part, s_wsum);
    }
    grid_bar();

    // ---- data-dependent while loop, fully on-device ----
    for (int it = 0; it < MAX_IT; it++) {
        // decide: parallel load of g_part into smem, fixed-order sum by thread
        // 0 -> identical double in every block -> identical branch.
        for (int i = threadIdx.x; i < (int)gridDim.x; i += TPB)
            s_pg[i] = ((volatile double*)g_part)[i];
        __syncthreads();
        if (threadIdx.x == 0) {
            double s = 0.0;
            for (int i = 0; i < (int)gridDim.x; i++) s += s_pg[i];
            s_bcast = s;
        }
        __syncthreads();
        double tot = s_bcast;
        __syncthreads();
        if (!(tot < THRESH)) break;   // NaN-safe, same as jnp semantics

        float part = 0.f;
        // software-pipelined grid-stride: prefetch next pixel while computing
        unsigned long long vp[8];
        {
            const ulonglong2* p2 = (const ulonglong2*)(g_v + (size_t)gid * 8);
            if (gid < NPIX) {
                ulonglong2 t0 = p2[0], t1 = p2[1], t2 = p2[2], t3 = p2[3];
                vp[0]=t0.x; vp[1]=t0.y; vp[2]=t1.x; vp[3]=t1.y;
                vp[4]=t2.x; vp[5]=t2.y; vp[6]=t3.x; vp[7]=t3.y;
            }
        }
        for (int q = gid; q < NPIX; q += stride) {
            unsigned long long vn[8];
            int qn = q + stride;
            if (qn < NPIX) {
                const ulonglong2* p2 = (const ulonglong2*)(g_v + (size_t)qn * 8);
                ulonglong2 t0 = p2[0], t1 = p2[1], t2 = p2[2], t3 = p2[3];
                vn[0]=t0.x; vn[1]=t0.y; vn[2]=t1.x; vn[3]=t1.y;
                vn[4]=t2.x; vn[5]=t2.y; vn[6]=t3.x; vn[7]=t3.y;
            }
            // conv w_shared + tanh -> hp (channel-pair packed)
            unsigned long long hp[8];
            #pragma unroll
            for (int o = 0; o < COUT; o += 2) {
                unsigned long long a0 = pack2(s_bsh[o], 0.0f);
                unsigned long long a1 = pack2(s_bsh[o + 1], 0.0f);
                #pragma unroll
                for (int j = 0; j < 8; j++) {
                    a0 = ffma2(s_wsh2[o * 8 + j],       vp[j], a0);
                    a1 = ffma2(s_wsh2[(o + 1) * 8 + j], vp[j], a1);
                }
                hp[o >> 1] = pack2(tanhx(hadd2(a0)), tanhx(hadd2(a1)));
            }
            // conv w_loop, *10, store packed, accumulate |.|
            ulonglong2* vp2 = (ulonglong2*)(g_v + (size_t)q * 8);
            #pragma unroll
            for (int o = 0; o < COUT; o += 4) {
                unsigned long long a0 = pack2(s_bl[o], 0.0f);
                unsigned long long a1 = pack2(s_bl[o + 1], 0.0f);
                unsigned long long a2 = pack2(s_bl[o + 2], 0.0f);
                unsigned long long a3 = pack2(s_bl[o + 3], 0.0f);
                #pragma unroll
                for (int j = 0; j < 8; j++) {
                    a0 = ffma2(s_wl2[o * 8 + j],       hp[j], a0);
                    a1 = ffma2(s_wl2[(o + 1) * 8 + j], hp[j], a1);
                    a2 = ffma2(s_wl2[(o + 2) * 8 + j], hp[j], a2);
                    a3 = ffma2(s_wl2[(o + 3) * 8 + j], hp[j], a3);
                }
                float s0 = hadd2(a0) * 10.0f, s1 = hadd2(a1) * 10.0f;
                float s2 = hadd2(a2) * 10.0f, s3 = hadd2(a3) * 10.0f;
                part += fabsf(s0) + fabsf(s1) + fabsf(s2) + fabsf(s3);
                vp2[o >> 2] = make_ulonglong2(pack2(s0, s1), pack2(s2, s3));
            }
            #pragma unroll
            for (int j = 0; j < 8; j++) vp[j] = vn[j];
        }
        store_block_partial(part, s_wsum);
        grid_bar();
    }

    // ---- final conv w_shared (v packed -> out planar) ----
    {
        int b = b0i, i = i0i;
        for (int q = gid; q < NPIX; q += stride) {
            const ulonglong2* p2 = (const ulonglong2*)(g_v + (size_t)q * 8);
            ulonglong2 t0 = p2[0], t1 = p2[1], t2 = p2[2], t3 = p2[3];
            unsigned long long vp[8] = {t0.x, t0.y, t1.x, t1.y,
                                        t2.x, t2.y, t3.x, t3.y};
            float* op = out + (size_t)b * (COUT * HW) + i;
            #pragma unroll
            for (int o = 0; o < COUT; o++) {
                unsigned long long a = pack2(s_bsh[o], 0.0f);
                #pragma unroll
                for (int j = 0; j < 8; j++) a = ffma2(s_wsh2[o * 8 + j], vp[j], a);
                op[(size_t)o * HW] = hadd2(a);
            }
            i += stride;
            while (i >= HW) { i -= HW; b++; }
        }
    }
}

extern "C" void kernel_launch(void* const* d_in, const int* in_sizes, int n_in,
                              void* d_out, int out_size) {
    const float* x     = (const float*)d_in[0];
    const float* wpre  = (const float*)d_in[1];
    const float* bpre  = (const float*)d_in[2];
    const float* wloop = (const float*)d_in[3];
    const float* bloop = (const float*)d_in[4];
    const float* wsh   = (const float*)d_in[5];
    const float* bsh   = (const float*)d_in[6];
    (void)in_sizes; (void)n_in; (void)out_size;

    int dev = 0;
    cudaGetDevice(&dev);
    int sms = 0;
    cudaDeviceGetAttribute(&sms, cudaDevAttrMultiProcessorCount, dev);
    if (sms < 1) sms = 148;

    // Co-residency verified, not assumed: barrier is deadlock-free iff
    // gridDim <= sms * blocksPerSM.
    int occ = 0;
    cudaOccupancyMaxActiveBlocksPerMultiprocessor(&occ, control_while_kernel,
                                                  TPB, 0);
    if (occ < 1) occ = 1;
    long long want = (long long)sms * occ;     // use all co-resident slots
    int blocks = (want > MAX_BLOCKS) ? MAX_BLOCKS : (int)want;

    control_while_kernel<<<blocks, TPB>>>(x, wpre, bpre, wloop, bloop, wsh, bsh,
                                          (float*)d_out);
}